// round 15
// baseline (speedup 1.0000x reference)
#include <cuda_runtime.h>
#include <cuda_fp16.h>
#include <cstdint>
#include <cstring>

#define N_NODES 50000
#define N_EDGES 1600000
#define D 128
#define SLOPE 0.01f
#define SCAN_TPB 512
#define SCAN_BLOCKS 98            // 98*512 = 50176 >= 50001
#define GT 128
#define NTILES ((N_NODES + 63) / 64)
// merged prep kernel block ranges — COUNT FIRST (critical path), then cvt, then wt
#define PREP_CNT_BLOCKS   1563    // covers N_EDGES/4 = 400,000
#define PREP_CVT_BLOCKS   6250    // 6250*256 = 1,600,000 = N_NODES*32
#define PREP_WT_BLOCKS    32      // 4 x 4 x 2 tiles
#define PREP_BLOCKS (PREP_CNT_BLOCKS + PREP_CVT_BLOCKS + PREP_WT_BLOCKS)
typedef unsigned long long ull;

// ---------------- scratch (device globals) -----------------------------------
__device__ int    g_cnt[N_NODES];
__device__ int    g_offs[N_NODES + 1];
__device__ int    g_rank[N_EDGES];
__device__ int    g_bsum[SCAN_BLOCKS];
__device__ int    g_ssrc[N_EDGES];
__device__ float4 g_H4[N_NODES * 32];
__device__ uint2  g_Eh[N_NODES * 32];    // f16 copy of E
__device__ float  g_W1T[D * D];          // [k][j]
__device__ float  g_W2T[D * D];

// ---------------- helpers -----------------------------------------------------
__device__ __forceinline__ void fma2(ull& acc, ull a, ull b) {
    asm("fma.rn.f32x2 %0, %1, %2, %0;" : "+l"(acc) : "l"(a), "l"(b));
}
__device__ __forceinline__ ull dup2(float x) {
    ull r; asm("mov.b64 %0, {%1, %1};" : "=l"(r) : "f"(x)); return r;
}
__device__ __forceinline__ float2 unpack2(ull v) {
    float2 f; asm("mov.b64 {%0, %1}, %2;" : "=f"(f.x), "=f"(f.y) : "l"(v)); return f;
}
__device__ __forceinline__ float lrelu(float x) { return fmaxf(x, SLOPE * x); }
__device__ __forceinline__ uint32_t h2_u32(__half2 h) {
    uint32_t u; memcpy(&u, &h, 4); return u;
}

// ---------------- merged prep: count | cvt | wt ---------------------------------
__global__ void k_prep(const float4* __restrict__ E4,
                       const int* __restrict__ dst,
                       const float* __restrict__ W1,
                       const float* __restrict__ W2) {
    int b = blockIdx.x;
    int tid = threadIdx.x;
    if (b < PREP_CNT_BLOCKS) {
        // ---- degree count + per-edge rank (critical path: starts first) ----
        int i = b * 256 + tid;
        if (i < N_EDGES / 4) {
            int4 d = ((const int4*)dst)[i];
            int4 r;
            r.x = atomicAdd(&g_cnt[d.x], 1);
            r.y = atomicAdd(&g_cnt[d.y], 1);
            r.z = atomicAdd(&g_cnt[d.z], 1);
            r.w = atomicAdd(&g_cnt[d.w], 1);
            ((int4*)g_rank)[i] = r;
        }
    } else if (b < PREP_CNT_BLOCKS + PREP_CVT_BLOCKS) {
        // ---- E f32 -> f16 (streams under the atomic-bound count) ----
        int i = (b - PREP_CNT_BLOCKS) * 256 + tid;
        float4 v = E4[i];
        uint2 o;
        o.x = h2_u32(__floats2half2_rn(v.x, v.y));
        o.y = h2_u32(__floats2half2_rn(v.z, v.w));
        g_Eh[i] = o;
    } else {
        // ---- weight transpose ----
        __shared__ float t[32][33];
        int id = b - PREP_CNT_BLOCKS - PREP_CVT_BLOCKS;   // 0..31
        int bxi = id & 3, byi = (id >> 2) & 3, z = id >> 4;
        const float* W = z ? W2 : W1;
        float* T = z ? g_W2T : g_W1T;
        int bx = bxi * 32, by = byi * 32;
        int tx = tid & 31, ty = tid >> 5;                 // 32 x 8
        for (int i = ty; i < 32; i += 8)
            t[i][tx] = W[(by + i) * D + bx + tx];
        __syncthreads();
        for (int i = ty; i < 32; i += 8)
            T[(bx + i) * D + by + tx] = t[tx][i];
    }
}

// ---------------- CSR scan ----------------------------------------------------
__global__ void k_scan1() {
    __shared__ int wsum[SCAN_TPB / 32];
    int tid = threadIdx.x, lane = tid & 31, wid = tid >> 5;
    int i = blockIdx.x * SCAN_TPB + tid;
    int v = (i < N_NODES) ? g_cnt[i] : 0;
    int x = v;
    #pragma unroll
    for (int o = 1; o < 32; o <<= 1) {
        int y = __shfl_up_sync(0xffffffffu, x, o);
        if (lane >= o) x += y;
    }
    if (lane == 31) wsum[wid] = x;
    __syncthreads();
    if (wid == 0) {
        int s = (lane < SCAN_TPB / 32) ? wsum[lane] : 0;
        #pragma unroll
        for (int o = 1; o < 32; o <<= 1) {
            int y = __shfl_up_sync(0xffffffffu, s, o);
            if (lane >= o) s += y;
        }
        if (lane < SCAN_TPB / 32) wsum[lane] = s;
    }
    __syncthreads();
    int excl = x - v + (wid ? wsum[wid - 1] : 0);
    if (i <= N_NODES) g_offs[i] = excl;
    if (tid == SCAN_TPB - 1) g_bsum[blockIdx.x] = excl + v;
}

__global__ void k_scan2() {
    __shared__ int wsum[4];
    int t = threadIdx.x, lane = t & 31, wid = t >> 5;
    int v = (t < SCAN_BLOCKS) ? g_bsum[t] : 0;
    int x = v;
    #pragma unroll
    for (int o = 1; o < 32; o <<= 1) {
        int y = __shfl_up_sync(0xffffffffu, x, o);
        if (lane >= o) x += y;
    }
    if (lane == 31) wsum[wid] = x;
    __syncthreads();
    if (wid == 0 && lane < 4) {
        int s = wsum[lane];
        #pragma unroll
        for (int o = 1; o < 4; o <<= 1) {
            int y = __shfl_up_sync(0xfu, s, o);
            if (lane >= o) s += y;
        }
        wsum[lane] = s;
    }
    __syncthreads();
    int excl = x - v + (wid ? wsum[wid - 1] : 0);
    if (t < SCAN_BLOCKS) g_bsum[t] = excl;
}

__global__ void k_fill(const int* __restrict__ src, const int* __restrict__ dst) {
    int i = blockIdx.x * blockDim.x + threadIdx.x;
    if (i < N_EDGES / 4) {
        int4 d = ((const int4*)dst)[i];
        int4 s = ((const int4*)src)[i];
        int4 r = ((const int4*)g_rank)[i];
        g_ssrc[g_offs[d.x] + g_bsum[d.x >> 9] + r.x] = s.x;
        g_ssrc[g_offs[d.y] + g_bsum[d.y >> 9] + r.y] = s.y;
        g_ssrc[g_offs[d.z] + g_bsum[d.z >> 9] + r.z] = s.z;
        g_ssrc[g_offs[d.w] + g_bsum[d.w >> 9] + r.w] = s.w;
    }
}

// ---------------- gather-sum: half-warp per edge, uint4 rows --------------------
// Warp w handles node w. Lanes 0-15 (half 0) process even edges, lanes 16-31
// (half 1) odd edges — two edges per warp-wide instruction. Each lane loads
// uint4 = 8 f16 dims; final cross-half shfl_xor(16) combine; lanes 0-15 store.
__device__ __forceinline__ void acc8(float* a, uint4 u) {
    float2 f;
    f = __half22float2(*(__half2*)&u.x); a[0] += f.x; a[1] += f.y;
    f = __half22float2(*(__half2*)&u.y); a[2] += f.x; a[3] += f.y;
    f = __half22float2(*(__half2*)&u.z); a[4] += f.x; a[5] += f.y;
    f = __half22float2(*(__half2*)&u.w); a[6] += f.x; a[7] += f.y;
}

__global__ void k_gather() {
    int w = (blockIdx.x * blockDim.x + threadIdx.x) >> 5;
    int lane = threadIdx.x & 31;
    if (w >= N_NODES) return;
    int half = lane >> 4, l16 = lane & 15;
    int beg = g_offs[w] + g_bsum[w >> 9];
    int end = g_offs[w + 1] + g_bsum[(w + 1) >> 9];
    const uint4* Eh4 = (const uint4*)g_Eh;   // 16 uint4 per node row

    float a0[8] = {0.f, 0.f, 0.f, 0.f, 0.f, 0.f, 0.f, 0.f};
    float a1[8] = {0.f, 0.f, 0.f, 0.f, 0.f, 0.f, 0.f, 0.f};

    int e = beg + half;
    for (; e + 2 < end; e += 4) {            // this half: edges e, e+2
        int s0 = g_ssrc[e];
        int s1 = g_ssrc[e + 2];
        uint4 u0 = Eh4[s0 * 16 + l16];
        uint4 u1 = Eh4[s1 * 16 + l16];
        acc8(a0, u0);
        acc8(a1, u1);
    }
    for (; e < end; e += 2) {
        int s = g_ssrc[e];
        uint4 u = Eh4[s * 16 + l16];
        acc8(a0, u);
    }
    #pragma unroll
    for (int i = 0; i < 8; i++) a0[i] += a1[i];
    #pragma unroll
    for (int i = 0; i < 8; i++) a0[i] += __shfl_xor_sync(0xffffffffu, a0[i], 16);
    if (half == 0) {
        float4* H = (float4*)g_H4;
        H[w * 32 + 2 * l16]     = make_float4(a0[0], a0[1], a0[2], a0[3]);
        H[w * 32 + 2 * l16 + 1] = make_float4(a0[4], a0[5], a0[6], a0[7]);
    }
}

// ---------------- dual GEMV + LeakyReLU (register-blocked, R11-proven) ----------
__device__ __forceinline__ void stepf(float h, float m,
                                      ulonglong2 w1a, ulonglong2 w1b,
                                      ulonglong2 w2a, ulonglong2 w2b,
                                      ull* aN, ull* aI) {
    ull h2 = dup2(h), m2 = dup2(m);
    fma2(aN[0], h2, w1a.x); fma2(aN[1], h2, w1a.y);
    fma2(aN[2], h2, w1b.x); fma2(aN[3], h2, w1b.y);
    fma2(aI[0], m2, w2a.x); fma2(aI[1], m2, w2a.y);
    fma2(aI[2], m2, w2b.x); fma2(aI[3], m2, w2b.y);
}

#define GEMM_SMEM ((2 * D * D + 2 * D * 64) * 4)

__global__ void __launch_bounds__(GT, 1)
k_gemm(const float4* __restrict__ E4,
       const float* __restrict__ b1, const float* __restrict__ b2,
       float* __restrict__ out) {
    extern __shared__ float sm[];
    float* sW1 = sm;
    float* sW2 = sm + D * D;
    float* sH  = sm + 2 * D * D;
    float* sM  = sH + D * 64;
    int tid = threadIdx.x;
    int lane16 = tid & 15, grp = tid >> 4;
    int j0 = lane16 * 8;

    {
        float4* d1 = (float4*)sW1; const float4* s1 = (const float4*)g_W1T;
        float4* d2 = (float4*)sW2; const float4* s2 = (const float4*)g_W2T;
        #pragma unroll
        for (int i = 0; i < D * D / 4 / GT; i++) {
            d1[i * GT + tid] = s1[i * GT + tid];
            d2[i * GT + tid] = s2[i * GT + tid];
        }
    }
    float4 b1a = *(const float4*)&b1[j0], b1b = *(const float4*)&b1[j0 + 4];
    float4 b2a = *(const float4*)&b2[j0], b2b = *(const float4*)&b2[j0 + 4];

    const ulonglong2* W1p = (const ulonglong2*)sW1;
    const ulonglong2* W2p = (const ulonglong2*)sW2;
    const float4* Hp = (const float4*)sH;
    const float4* Mp = (const float4*)sM;
    int wj = lane16 * 2;
    int hj = grp * 2;

    for (int t = blockIdx.x; t < NTILES; t += gridDim.x) {
        int nbase = t * 64;
        __syncthreads();
        #pragma unroll
        for (int it = 0; it < 8; it++) {
            int idx = it * GT + tid;
            int n = idx & 63, c8 = idx >> 6;
            int gn = nbase + n;
            float4 h0, h1, e0, e1;
            if (gn < N_NODES) {
                h0 = g_H4[gn * 32 + c8 * 2]; h1 = g_H4[gn * 32 + c8 * 2 + 1];
                e0 = E4[gn * 32 + c8 * 2];   e1 = E4[gn * 32 + c8 * 2 + 1];
            } else {
                h0 = h1 = e0 = e1 = make_float4(0.f, 0.f, 0.f, 0.f);
            }
            int k0 = c8 * 8;
            sH[(k0 + 0) * 64 + n] = h0.x; sH[(k0 + 1) * 64 + n] = h0.y;
            sH[(k0 + 2) * 64 + n] = h0.z; sH[(k0 + 3) * 64 + n] = h0.w;
            sH[(k0 + 4) * 64 + n] = h1.x; sH[(k0 + 5) * 64 + n] = h1.y;
            sH[(k0 + 6) * 64 + n] = h1.z; sH[(k0 + 7) * 64 + n] = h1.w;
            sM[(k0 + 0) * 64 + n] = e0.x * h0.x; sM[(k0 + 1) * 64 + n] = e0.y * h0.y;
            sM[(k0 + 2) * 64 + n] = e0.z * h0.z; sM[(k0 + 3) * 64 + n] = e0.w * h0.w;
            sM[(k0 + 4) * 64 + n] = e1.x * h1.x; sM[(k0 + 5) * 64 + n] = e1.y * h1.y;
            sM[(k0 + 6) * 64 + n] = e1.z * h1.z; sM[(k0 + 7) * 64 + n] = e1.w * h1.w;
        }
        __syncthreads();

        ull accN[8][4], accI[8][4];
        #pragma unroll
        for (int i = 0; i < 8; i++)
            #pragma unroll
            for (int c = 0; c < 4; c++) { accN[i][c] = 0ull; accI[i][c] = 0ull; }

        ulonglong2 w1aA, w1bA, w2aA, w2bA; float4 haA, hbA, maA, mbA;
        ulonglong2 w1aB, w1bB, w2aB, w2bB; float4 haB, hbB, maB, mbB;

#define LOADK(S, kk)                                                            \
        w1a##S = W1p[(kk) * 32 + wj]; w1b##S = W1p[(kk) * 32 + wj + 1];        \
        w2a##S = W2p[(kk) * 32 + wj]; w2b##S = W2p[(kk) * 32 + wj + 1];        \
        ha##S = Hp[(kk) * 16 + hj];   hb##S = Hp[(kk) * 16 + hj + 1];          \
        ma##S = Mp[(kk) * 16 + hj];   mb##S = Mp[(kk) * 16 + hj + 1];

#define COMPK(S)                                                                \
        stepf(ha##S.x, ma##S.x, w1a##S, w1b##S, w2a##S, w2b##S, accN[0], accI[0]); \
        stepf(ha##S.y, ma##S.y, w1a##S, w1b##S, w2a##S, w2b##S, accN[1], accI[1]); \
        stepf(ha##S.z, ma##S.z, w1a##S, w1b##S, w2a##S, w2b##S, accN[2], accI[2]); \
        stepf(ha##S.w, ma##S.w, w1a##S, w1b##S, w2a##S, w2b##S, accN[3], accI[3]); \
        stepf(hb##S.x, mb##S.x, w1a##S, w1b##S, w2a##S, w2b##S, accN[4], accI[4]); \
        stepf(hb##S.y, mb##S.y, w1a##S, w1b##S, w2a##S, w2b##S, accN[5], accI[5]); \
        stepf(hb##S.z, mb##S.z, w1a##S, w1b##S, w2a##S, w2b##S, accN[6], accI[6]); \
        stepf(hb##S.w, mb##S.w, w1a##S, w1b##S, w2a##S, w2b##S, accN[7], accI[7]);

        LOADK(A, 0)
        #pragma unroll 4
        for (int k = 0; k < D; k += 2) {
            LOADK(B, k + 1)
            COMPK(A)
            int k2 = (k + 2) & (D - 1);
            LOADK(A, k2)
            COMPK(B)
        }
#undef LOADK
#undef COMPK

        float b1r[8] = {b1a.x, b1a.y, b1a.z, b1a.w, b1b.x, b1b.y, b1b.z, b1b.w};
        float b2r[8] = {b2a.x, b2a.y, b2a.z, b2a.w, b2b.x, b2b.y, b2b.z, b2b.w};
        #pragma unroll
        for (int i = 0; i < 8; i++) {
            int n = nbase + grp * 8 + i;
            if (n < N_NODES) {
                float o[8];
                #pragma unroll
                for (int c = 0; c < 4; c++) {
                    float2 vN = unpack2(accN[i][c]);
                    float2 vI = unpack2(accI[i][c]);
                    o[2 * c]     = lrelu(vN.x + b1r[2 * c])     + lrelu(vI.x + b2r[2 * c]);
                    o[2 * c + 1] = lrelu(vN.y + b1r[2 * c + 1]) + lrelu(vI.y + b2r[2 * c + 1]);
                }
                *(float4*)&out[n * D + j0]     = make_float4(o[0], o[1], o[2], o[3]);
                *(float4*)&out[n * D + j0 + 4] = make_float4(o[4], o[5], o[6], o[7]);
            }
        }
    }
}

// ---------------- launch --------------------------------------------------------
extern "C" void kernel_launch(void* const* d_in, const int* in_sizes, int n_in,
                              void* d_out, int out_size) {
    const float* entity = (const float*)d_in[0];
    const float* W1 = (const float*)d_in[1];
    const float* b1 = (const float*)d_in[2];
    const float* W2 = (const float*)d_in[3];
    const float* b2 = (const float*)d_in[4];
    const int*   src = (const int*)d_in[5];
    const int*   dst = (const int*)d_in[6];
    float* out = (float*)d_out;
    const float4* E4 = (const float4*)entity;

    static void* cnt_addr = nullptr;
    if (!cnt_addr) {
        cudaGetSymbolAddress(&cnt_addr, g_cnt);
        cudaFuncSetAttribute(k_gemm, cudaFuncAttributeMaxDynamicSharedMemorySize, GEMM_SMEM);
    }

    cudaMemsetAsync(cnt_addr, 0, N_NODES * sizeof(int));
    k_prep<<<PREP_BLOCKS, 256>>>(E4, dst, W1, W2);
    k_scan1<<<SCAN_BLOCKS, SCAN_TPB>>>();
    k_scan2<<<1, 128>>>();
    k_fill<<<(N_EDGES / 4 + 255) / 256, 256>>>(src, dst);
    k_gather<<<(N_NODES * 32 + 255) / 256, 256>>>();
    k_gemm<<<148, GT, GEMM_SMEM>>>(E4, b1, b2, out);
}

// round 16
// speedup vs baseline: 1.0652x; 1.0652x over previous
#include <cuda_runtime.h>
#include <cuda_fp16.h>
#include <cstdint>
#include <cstring>

#define N_NODES 50000
#define N_EDGES 1600000
#define D 128
#define SLOPE 0.01f
#define SCAN_TPB 512
#define SCAN_BLOCKS 98            // 98*512 = 50176 >= 50001
#define GT 128
#define NTILES ((N_NODES + 63) / 64)
// merged prep kernel block ranges — COUNT FIRST (critical path), then cvt, then wt
#define PREP_CNT_BLOCKS   1563    // covers N_EDGES/4 = 400,000
#define PREP_CVT_BLOCKS   6250    // 6250*256 = 1,600,000 = N_NODES*32
#define PREP_WT_BLOCKS    32      // 4 x 4 x 2 tiles
#define PREP_BLOCKS (PREP_CNT_BLOCKS + PREP_CVT_BLOCKS + PREP_WT_BLOCKS)
typedef unsigned long long ull;

// ---------------- scratch (device globals) -----------------------------------
__device__ int      g_cnt[N_NODES];
__device__ int      g_offs[N_NODES + 1];
__device__ unsigned g_pack[N_EDGES];     // (dst << 16) | rank
__device__ int      g_bsum[SCAN_BLOCKS];
__device__ int      g_ssrc[N_EDGES];
__device__ uint2    g_Hh[N_NODES * 32];  // f16 H (4 dims per uint2)
__device__ uint2    g_Eh[N_NODES * 32];  // f16 copy of E
__device__ float    g_W1T[D * D];        // [k][j]
__device__ float    g_W2T[D * D];

// ---------------- helpers -----------------------------------------------------
__device__ __forceinline__ void fma2(ull& acc, ull a, ull b) {
    asm("fma.rn.f32x2 %0, %1, %2, %0;" : "+l"(acc) : "l"(a), "l"(b));
}
__device__ __forceinline__ ull dup2(float x) {
    ull r; asm("mov.b64 %0, {%1, %1};" : "=l"(r) : "f"(x)); return r;
}
__device__ __forceinline__ float2 unpack2(ull v) {
    float2 f; asm("mov.b64 {%0, %1}, %2;" : "=f"(f.x), "=f"(f.y) : "l"(v)); return f;
}
__device__ __forceinline__ float lrelu(float x) { return fmaxf(x, SLOPE * x); }
__device__ __forceinline__ uint32_t h2_u32(__half2 h) {
    uint32_t u; memcpy(&u, &h, 4); return u;
}
__device__ __forceinline__ float4 u2_f4(uint2 u) {
    float2 a = __half22float2(*(__half2*)&u.x);
    float2 b = __half22float2(*(__half2*)&u.y);
    return make_float4(a.x, a.y, b.x, b.y);
}

// ---------------- merged prep: count | cvt | wt ---------------------------------
__global__ void k_prep(const float4* __restrict__ E4,
                       const int* __restrict__ dst,
                       const float* __restrict__ W1,
                       const float* __restrict__ W2) {
    int b = blockIdx.x;
    int tid = threadIdx.x;
    if (b < PREP_CNT_BLOCKS) {
        // ---- degree count + packed (dst,rank) ----
        int i = b * 256 + tid;
        if (i < N_EDGES / 4) {
            int4 d = ((const int4*)dst)[i];
            uint4 p;
            p.x = ((unsigned)d.x << 16) | (unsigned)atomicAdd(&g_cnt[d.x], 1);
            p.y = ((unsigned)d.y << 16) | (unsigned)atomicAdd(&g_cnt[d.y], 1);
            p.z = ((unsigned)d.z << 16) | (unsigned)atomicAdd(&g_cnt[d.z], 1);
            p.w = ((unsigned)d.w << 16) | (unsigned)atomicAdd(&g_cnt[d.w], 1);
            ((uint4*)g_pack)[i] = p;
        }
    } else if (b < PREP_CNT_BLOCKS + PREP_CVT_BLOCKS) {
        // ---- E f32 -> f16 (streams under the atomic-bound count) ----
        int i = (b - PREP_CNT_BLOCKS) * 256 + tid;
        float4 v = E4[i];
        uint2 o;
        o.x = h2_u32(__floats2half2_rn(v.x, v.y));
        o.y = h2_u32(__floats2half2_rn(v.z, v.w));
        g_Eh[i] = o;
    } else {
        // ---- weight transpose ----
        __shared__ float t[32][33];
        int id = b - PREP_CNT_BLOCKS - PREP_CVT_BLOCKS;   // 0..31
        int bxi = id & 3, byi = (id >> 2) & 3, z = id >> 4;
        const float* W = z ? W2 : W1;
        float* T = z ? g_W2T : g_W1T;
        int bx = bxi * 32, by = byi * 32;
        int tx = tid & 31, ty = tid >> 5;                 // 32 x 8
        for (int i = ty; i < 32; i += 8)
            t[i][tx] = W[(by + i) * D + bx + tx];
        __syncthreads();
        for (int i = ty; i < 32; i += 8)
            T[(bx + i) * D + by + tx] = t[tx][i];
    }
}

// ---------------- CSR scan ----------------------------------------------------
__global__ void k_scan1() {
    __shared__ int wsum[SCAN_TPB / 32];
    int tid = threadIdx.x, lane = tid & 31, wid = tid >> 5;
    int i = blockIdx.x * SCAN_TPB + tid;
    int v = (i < N_NODES) ? g_cnt[i] : 0;
    int x = v;
    #pragma unroll
    for (int o = 1; o < 32; o <<= 1) {
        int y = __shfl_up_sync(0xffffffffu, x, o);
        if (lane >= o) x += y;
    }
    if (lane == 31) wsum[wid] = x;
    __syncthreads();
    if (wid == 0) {
        int s = (lane < SCAN_TPB / 32) ? wsum[lane] : 0;
        #pragma unroll
        for (int o = 1; o < 32; o <<= 1) {
            int y = __shfl_up_sync(0xffffffffu, s, o);
            if (lane >= o) s += y;
        }
        if (lane < SCAN_TPB / 32) wsum[lane] = s;
    }
    __syncthreads();
    int excl = x - v + (wid ? wsum[wid - 1] : 0);
    if (i <= N_NODES) g_offs[i] = excl;
    if (tid == SCAN_TPB - 1) g_bsum[blockIdx.x] = excl + v;
}

__global__ void k_scan2() {
    __shared__ int wsum[4];
    int t = threadIdx.x, lane = t & 31, wid = t >> 5;
    int v = (t < SCAN_BLOCKS) ? g_bsum[t] : 0;
    int x = v;
    #pragma unroll
    for (int o = 1; o < 32; o <<= 1) {
        int y = __shfl_up_sync(0xffffffffu, x, o);
        if (lane >= o) x += y;
    }
    if (lane == 31) wsum[wid] = x;
    __syncthreads();
    if (wid == 0 && lane < 4) {
        int s = wsum[lane];
        #pragma unroll
        for (int o = 1; o < 4; o <<= 1) {
            int y = __shfl_up_sync(0xfu, s, o);
            if (lane >= o) s += y;
        }
        wsum[lane] = s;
    }
    __syncthreads();
    int excl = x - v + (wid ? wsum[wid - 1] : 0);
    if (t < SCAN_BLOCKS) g_bsum[t] = excl;
}

__global__ void k_fill(const int* __restrict__ src) {
    int i = blockIdx.x * blockDim.x + threadIdx.x;
    if (i < N_EDGES / 4) {
        uint4 p = ((const uint4*)g_pack)[i];
        int4 s = ((const int4*)src)[i];
        unsigned dx = p.x >> 16, dy = p.y >> 16, dz = p.z >> 16, dw = p.w >> 16;
        g_ssrc[g_offs[dx] + g_bsum[dx >> 9] + (p.x & 0xffffu)] = s.x;
        g_ssrc[g_offs[dy] + g_bsum[dy >> 9] + (p.y & 0xffffu)] = s.y;
        g_ssrc[g_offs[dz] + g_bsum[dz >> 9] + (p.z & 0xffffu)] = s.z;
        g_ssrc[g_offs[dw] + g_bsum[dw >> 9] + (p.w & 0xffffu)] = s.w;
    }
}

// ---------------- gather-sum (one warp per node, f16 rows, unroll-4) ------------
__device__ __forceinline__ void acc_h(float4& a, uint2 u) {
    float2 f01 = __half22float2(*(__half2*)&u.x);
    float2 f23 = __half22float2(*(__half2*)&u.y);
    a.x += f01.x; a.y += f01.y; a.z += f23.x; a.w += f23.y;
}

__global__ void k_gather() {
    int w = (blockIdx.x * blockDim.x + threadIdx.x) >> 5;
    int lane = threadIdx.x & 31;
    if (w >= N_NODES) return;
    int beg = g_offs[w] + g_bsum[w >> 9];
    int end = g_offs[w + 1] + g_bsum[(w + 1) >> 9];
    float4 a0 = make_float4(0.f, 0.f, 0.f, 0.f);
    float4 a1 = a0, a2 = a0, a3 = a0;
    int e = beg;
    for (; e + 3 < end; e += 4) {
        int s0 = g_ssrc[e], s1 = g_ssrc[e + 1], s2 = g_ssrc[e + 2], s3 = g_ssrc[e + 3];
        uint2 u0 = g_Eh[s0 * 32 + lane];
        uint2 u1 = g_Eh[s1 * 32 + lane];
        uint2 u2 = g_Eh[s2 * 32 + lane];
        uint2 u3 = g_Eh[s3 * 32 + lane];
        acc_h(a0, u0); acc_h(a1, u1); acc_h(a2, u2); acc_h(a3, u3);
    }
    for (; e < end; e++) {
        int s = g_ssrc[e];
        uint2 u = g_Eh[s * 32 + lane];
        acc_h(a0, u);
    }
    a0.x += a1.x + a2.x + a3.x;
    a0.y += a1.y + a2.y + a3.y;
    a0.z += a1.z + a2.z + a3.z;
    a0.w += a1.w + a2.w + a3.w;
    uint2 o;
    o.x = h2_u32(__floats2half2_rn(a0.x, a0.y));
    o.y = h2_u32(__floats2half2_rn(a0.z, a0.w));
    g_Hh[w * 32 + lane] = o;
}

// ---------------- dual GEMV + LeakyReLU (register-blocked, R11-proven) ----------
__device__ __forceinline__ void stepf(float h, float m,
                                      ulonglong2 w1a, ulonglong2 w1b,
                                      ulonglong2 w2a, ulonglong2 w2b,
                                      ull* aN, ull* aI) {
    ull h2 = dup2(h), m2 = dup2(m);
    fma2(aN[0], h2, w1a.x); fma2(aN[1], h2, w1a.y);
    fma2(aN[2], h2, w1b.x); fma2(aN[3], h2, w1b.y);
    fma2(aI[0], m2, w2a.x); fma2(aI[1], m2, w2a.y);
    fma2(aI[2], m2, w2b.x); fma2(aI[3], m2, w2b.y);
}

#define GEMM_SMEM ((2 * D * D + 2 * D * 64) * 4)

__global__ void __launch_bounds__(GT, 1)
k_gemm(const float4* __restrict__ E4,
       const float* __restrict__ b1, const float* __restrict__ b2,
       float* __restrict__ out) {
    extern __shared__ float sm[];
    float* sW1 = sm;
    float* sW2 = sm + D * D;
    float* sH  = sm + 2 * D * D;
    float* sM  = sH + D * 64;
    int tid = threadIdx.x;
    int lane16 = tid & 15, grp = tid >> 4;
    int j0 = lane16 * 8;

    {
        float4* d1 = (float4*)sW1; const float4* s1 = (const float4*)g_W1T;
        float4* d2 = (float4*)sW2; const float4* s2 = (const float4*)g_W2T;
        #pragma unroll
        for (int i = 0; i < D * D / 4 / GT; i++) {
            d1[i * GT + tid] = s1[i * GT + tid];
            d2[i * GT + tid] = s2[i * GT + tid];
        }
    }
    float4 b1a = *(const float4*)&b1[j0], b1b = *(const float4*)&b1[j0 + 4];
    float4 b2a = *(const float4*)&b2[j0], b2b = *(const float4*)&b2[j0 + 4];

    const ulonglong2* W1p = (const ulonglong2*)sW1;
    const ulonglong2* W2p = (const ulonglong2*)sW2;
    const float4* Hp = (const float4*)sH;
    const float4* Mp = (const float4*)sM;
    int wj = lane16 * 2;
    int hj = grp * 2;

    for (int t = blockIdx.x; t < NTILES; t += gridDim.x) {
        int nbase = t * 64;
        __syncthreads();
        #pragma unroll
        for (int it = 0; it < 8; it++) {
            int idx = it * GT + tid;
            int n = idx & 63, c8 = idx >> 6;
            int gn = nbase + n;
            float4 h0, h1, e0, e1;
            if (gn < N_NODES) {
                h0 = u2_f4(g_Hh[gn * 32 + c8 * 2]);
                h1 = u2_f4(g_Hh[gn * 32 + c8 * 2 + 1]);
                e0 = E4[gn * 32 + c8 * 2];
                e1 = E4[gn * 32 + c8 * 2 + 1];
            } else {
                h0 = h1 = e0 = e1 = make_float4(0.f, 0.f, 0.f, 0.f);
            }
            int k0 = c8 * 8;
            sH[(k0 + 0) * 64 + n] = h0.x; sH[(k0 + 1) * 64 + n] = h0.y;
            sH[(k0 + 2) * 64 + n] = h0.z; sH[(k0 + 3) * 64 + n] = h0.w;
            sH[(k0 + 4) * 64 + n] = h1.x; sH[(k0 + 5) * 64 + n] = h1.y;
            sH[(k0 + 6) * 64 + n] = h1.z; sH[(k0 + 7) * 64 + n] = h1.w;
            sM[(k0 + 0) * 64 + n] = e0.x * h0.x; sM[(k0 + 1) * 64 + n] = e0.y * h0.y;
            sM[(k0 + 2) * 64 + n] = e0.z * h0.z; sM[(k0 + 3) * 64 + n] = e0.w * h0.w;
            sM[(k0 + 4) * 64 + n] = e1.x * h1.x; sM[(k0 + 5) * 64 + n] = e1.y * h1.y;
            sM[(k0 + 6) * 64 + n] = e1.z * h1.z; sM[(k0 + 7) * 64 + n] = e1.w * h1.w;
        }
        __syncthreads();

        ull accN[8][4], accI[8][4];
        #pragma unroll
        for (int i = 0; i < 8; i++)
            #pragma unroll
            for (int c = 0; c < 4; c++) { accN[i][c] = 0ull; accI[i][c] = 0ull; }

        ulonglong2 w1aA, w1bA, w2aA, w2bA; float4 haA, hbA, maA, mbA;
        ulonglong2 w1aB, w1bB, w2aB, w2bB; float4 haB, hbB, maB, mbB;

#define LOADK(S, kk)                                                            \
        w1a##S = W1p[(kk) * 32 + wj]; w1b##S = W1p[(kk) * 32 + wj + 1];        \
        w2a##S = W2p[(kk) * 32 + wj]; w2b##S = W2p[(kk) * 32 + wj + 1];        \
        ha##S = Hp[(kk) * 16 + hj];   hb##S = Hp[(kk) * 16 + hj + 1];          \
        ma##S = Mp[(kk) * 16 + hj];   mb##S = Mp[(kk) * 16 + hj + 1];

#define COMPK(S)                                                                \
        stepf(ha##S.x, ma##S.x, w1a##S, w1b##S, w2a##S, w2b##S, accN[0], accI[0]); \
        stepf(ha##S.y, ma##S.y, w1a##S, w1b##S, w2a##S, w2b##S, accN[1], accI[1]); \
        stepf(ha##S.z, ma##S.z, w1a##S, w1b##S, w2a##S, w2b##S, accN[2], accI[2]); \
        stepf(ha##S.w, ma##S.w, w1a##S, w1b##S, w2a##S, w2b##S, accN[3], accI[3]); \
        stepf(hb##S.x, mb##S.x, w1a##S, w1b##S, w2a##S, w2b##S, accN[4], accI[4]); \
        stepf(hb##S.y, mb##S.y, w1a##S, w1b##S, w2a##S, w2b##S, accN[5], accI[5]); \
        stepf(hb##S.z, mb##S.z, w1a##S, w1b##S, w2a##S, w2b##S, accN[6], accI[6]); \
        stepf(hb##S.w, mb##S.w, w1a##S, w1b##S, w2a##S, w2b##S, accN[7], accI[7]);

        LOADK(A, 0)
        #pragma unroll 4
        for (int k = 0; k < D; k += 2) {
            LOADK(B, k + 1)
            COMPK(A)
            int k2 = (k + 2) & (D - 1);
            LOADK(A, k2)
            COMPK(B)
        }
#undef LOADK
#undef COMPK

        float b1r[8] = {b1a.x, b1a.y, b1a.z, b1a.w, b1b.x, b1b.y, b1b.z, b1b.w};
        float b2r[8] = {b2a.x, b2a.y, b2a.z, b2a.w, b2b.x, b2b.y, b2b.z, b2b.w};
        #pragma unroll
        for (int i = 0; i < 8; i++) {
            int n = nbase + grp * 8 + i;
            if (n < N_NODES) {
                float o[8];
                #pragma unroll
                for (int c = 0; c < 4; c++) {
                    float2 vN = unpack2(accN[i][c]);
                    float2 vI = unpack2(accI[i][c]);
                    o[2 * c]     = lrelu(vN.x + b1r[2 * c])     + lrelu(vI.x + b2r[2 * c]);
                    o[2 * c + 1] = lrelu(vN.y + b1r[2 * c + 1]) + lrelu(vI.y + b2r[2 * c + 1]);
                }
                *(float4*)&out[n * D + j0]     = make_float4(o[0], o[1], o[2], o[3]);
                *(float4*)&out[n * D + j0 + 4] = make_float4(o[4], o[5], o[6], o[7]);
            }
        }
    }
}

// ---------------- launch --------------------------------------------------------
extern "C" void kernel_launch(void* const* d_in, const int* in_sizes, int n_in,
                              void* d_out, int out_size) {
    const float* entity = (const float*)d_in[0];
    const float* W1 = (const float*)d_in[1];
    const float* b1 = (const float*)d_in[2];
    const float* W2 = (const float*)d_in[3];
    const float* b2 = (const float*)d_in[4];
    const int*   src = (const int*)d_in[5];
    const int*   dst = (const int*)d_in[6];
    float* out = (float*)d_out;
    const float4* E4 = (const float4*)entity;

    static void* cnt_addr = nullptr;
    if (!cnt_addr) {
        cudaGetSymbolAddress(&cnt_addr, g_cnt);
        cudaFuncSetAttribute(k_gemm, cudaFuncAttributeMaxDynamicSharedMemorySize, GEMM_SMEM);
    }

    cudaMemsetAsync(cnt_addr, 0, N_NODES * sizeof(int));
    k_prep<<<PREP_BLOCKS, 256>>>(E4, dst, W1, W2);
    k_scan1<<<SCAN_BLOCKS, SCAN_TPB>>>();
    k_scan2<<<1, 128>>>();
    k_fill<<<(N_EDGES / 4 + 255) / 256, 256>>>(src);
    k_gather<<<(N_NODES * 32 + 255) / 256, 256>>>();
    k_gemm<<<148, GT, GEMM_SMEM>>>(E4, b1, b2, out);
}